// round 2
// baseline (speedup 1.0000x reference)
#include <cuda_runtime.h>
#include <stdint.h>

#define BS 8
#define CH 256
#define HH 128
#define WW 128
#define HW (HH*WW)          /* 16384 */
#define NA 9
#define KTOP 100
#define NDET (BS*KTOP)      /* 800 */
#define FDIM (CH*NA)        /* 2304 */
#define HID 1024
#define NBINS 4096
#define CANDCAP 4096
#define BHW (NA*HW)         /* 147456 */
#define HMTOT (BS*BHW)      /* 1179648 */

// output offsets (floats)
#define OFF_HM    0
#define OFF_WH1   1179648
#define OFF_OFF1  1182848
#define OFF_CLS1  1184448
#define OFF_WH2   1185248
#define OFF_OFF2  1188448
#define OFF_S2CLS 1190048
#define OFF_S2WH  1198048
#define OFF_INDS  1201248
#define OFF_VAL   1202048

// ---------------- scratch (no allocations allowed) ----------------
__device__ int                g_hist[BS*NBINS];
__device__ int                g_thresh[BS];
__device__ int                g_ccnt[BS];
__device__ unsigned long long g_cand[BS*CANDCAP];
__device__ float              g_tv[NDET];
__device__ int                g_ti[NDET];
__device__ float              g_boxes[NDET*4];
__device__ float              g_roif[NDET*FDIM];   // [det][pt*256+c]
__device__ float              g_wp[FDIM*HID];      // permuted w_fc1
__device__ float              g_hdn[NDET*HID];

// ---------------- 1. zero hist + counters ----------------
__global__ void k_zero() {
    int i = blockIdx.x * blockDim.x + threadIdx.x;
    if (i < BS*NBINS) g_hist[i] = 0;
    if (i < BS)       g_ccnt[i] = 0;
}

// ---------------- 2. copy hm to out + histogram ----------------
__global__ void k_hist_copy(const float* __restrict__ hm, float* __restrict__ out) {
    int i = blockIdx.x * blockDim.x + threadIdx.x;
    if (i >= HMTOT) return;
    float v = hm[i];
    out[OFF_HM + i] = v;
    int b = i / BHW;
    int bin = (int)(v * (float)NBINS);
    bin = bin < 0 ? 0 : (bin > NBINS-1 ? NBINS-1 : bin);
    atomicAdd(&g_hist[b*NBINS + bin], 1);
}

// ---------------- 3. find threshold bin per batch ----------------
__global__ void k_thresh() {
    int b = threadIdx.x;
    if (b >= BS) return;
    int cum = 0;
    int t = 0;
    for (int bin = NBINS-1; bin >= 0; --bin) {
        cum += g_hist[b*NBINS + bin];
        if (cum >= KTOP) { t = bin; break; }
    }
    g_thresh[b] = t;
}

// ---------------- 4. collect candidates ----------------
__global__ void k_collect(const float* __restrict__ hm) {
    int i = blockIdx.x * blockDim.x + threadIdx.x;
    if (i >= HMTOT) return;
    float v = hm[i];
    int b = i / BHW;
    int bin = (int)(v * (float)NBINS);
    bin = bin < 0 ? 0 : (bin > NBINS-1 ? NBINS-1 : bin);
    if (bin < g_thresh[b]) return;
    int il  = i - b*BHW;
    int a   = il / HW;
    int pix = il - a*HW;
    unsigned int iflat = (unsigned int)(pix * NA + a);
    unsigned int vb = __float_as_uint(v);   // v >= 0 -> bits monotonic
    unsigned long long key = ((unsigned long long)vb << 32) | (0xFFFFFFFFu - iflat);
    int pos = atomicAdd(&g_ccnt[b], 1);
    if (pos < CANDCAP) g_cand[b*CANDCAP + pos] = key;
}

// ---------------- 5. exact sorted top-100 per batch ----------------
__global__ void k_select() {
    __shared__ unsigned long long sk[CANDCAP];
    __shared__ unsigned long long wmax[8];
    __shared__ unsigned long long sbest;
    int b = blockIdx.x;
    int tid = threadIdx.x;
    int C = g_ccnt[b]; if (C > CANDCAP) C = CANDCAP;
    for (int i = tid; i < CANDCAP; i += 256)
        sk[i] = (i < C) ? g_cand[b*CANDCAP + i] : 0ULL;
    __syncthreads();
    int lane = tid & 31, wid = tid >> 5;
    for (int r = 0; r < KTOP; ++r) {
        unsigned long long best = 0ULL;
        for (int i = tid; i < C; i += 256) {
            unsigned long long k = sk[i];
            if (k > best) best = k;
        }
        #pragma unroll
        for (int o = 16; o > 0; o >>= 1) {
            unsigned long long other = __shfl_xor_sync(0xffffffffu, best, o);
            if (other > best) best = other;
        }
        if (lane == 0) wmax[wid] = best;
        __syncthreads();
        if (tid == 0) {
            unsigned long long m = wmax[0];
            #pragma unroll
            for (int w = 1; w < 8; ++w) if (wmax[w] > m) m = wmax[w];
            sbest = m;
        }
        __syncthreads();
        unsigned long long m = sbest;
        for (int i = tid; i < C; i += 256) {
            if (sk[i] == m) {
                sk[i] = 0ULL;
                g_tv[b*KTOP + r] = __uint_as_float((unsigned int)(m >> 32));
                g_ti[b*KTOP + r] = (int)(0xFFFFFFFFu - (unsigned int)(m & 0xFFFFFFFFu));
            }
        }
        __syncthreads();
    }
}

// ---------------- 6. detections: gathers + boxes + small outputs ----------------
__global__ void k_detect(const float* __restrict__ wh, const float* __restrict__ offs,
                         float* __restrict__ out) {
    int j = blockIdx.x * blockDim.x + threadIdx.x;
    if (j >= NDET) return;
    int b = j / KTOP;
    float v   = g_tv[j];
    int iflat = g_ti[j];
    int cls1  = iflat % NA;
    int pos   = iflat / NA;           // < HW
    int inds  = pos + b * HW;
    // select_tensor quirk: t[inds] with inds < hw*9 -> batch 0, a=inds%9, p=inds/9
    int a2 = inds % NA;
    int p2 = inds / NA;
    float w0 = wh[(a2*4+0)*HW + p2];
    float w1 = wh[(a2*4+1)*HW + p2];
    float w2 = wh[(a2*4+2)*HW + p2];
    float w3 = wh[(a2*4+3)*HW + p2];
    float o0 = offs[(a2*2+0)*HW + p2];
    float o1 = offs[(a2*2+1)*HW + p2];
    float xs = (float)(inds % WW) + o0;
    float ys = (float)(inds / WW) + o1;
    float bx1 = xs + w0, by1 = ys + w1, bx2 = xs + w2, by2 = ys + w3;
    g_boxes[j*4+0] = bx1; g_boxes[j*4+1] = by1;
    g_boxes[j*4+2] = bx2; g_boxes[j*4+3] = by2;
    out[OFF_WH1 + j*4+0] = w0; out[OFF_WH1 + j*4+1] = w1;
    out[OFF_WH1 + j*4+2] = w2; out[OFF_WH1 + j*4+3] = w3;
    out[OFF_WH2 + j*4+0] = w0; out[OFF_WH2 + j*4+1] = w1;
    out[OFF_WH2 + j*4+2] = w2; out[OFF_WH2 + j*4+3] = w3;
    out[OFF_OFF1 + j*2+0] = o0; out[OFF_OFF1 + j*2+1] = o1;
    out[OFF_OFF2 + j*2+0] = o0; out[OFF_OFF2 + j*2+1] = o1;
    out[OFF_CLS1 + j] = (float)cls1;
    out[OFF_INDS + j] = (float)inds;
    out[OFF_VAL  + j] = v;
}

// ---------------- 7. ROI align 3x3 (one block per box, thread = channel) ----------------
__global__ void k_roi(const float* __restrict__ feat) {
    int j = blockIdx.x;
    int c = threadIdx.x;          // 256 channels
    int b = j / KTOP;
    float x1b = g_boxes[j*4+0], y1b = g_boxes[j*4+1];
    float x2b = g_boxes[j*4+2], y2b = g_boxes[j*4+3];
    float rw = fmaxf(x2b - x1b, 1.0f);
    float rh = fmaxf(y2b - y1b, 1.0f);
    float bw = rw / 3.0f;
    float bh = rh / 3.0f;
    const float* fb = feat + ((size_t)b*CH + c) * HW;
    #pragma unroll
    for (int pt = 0; pt < 9; ++pt) {
        int gy = pt / 3, gx = pt % 3;
        float sy = __fadd_rn(y1b, __fmul_rn((float)gy + 0.5f, bh));
        float sx = __fadd_rn(x1b, __fmul_rn((float)gx + 0.5f, bw));
        bool inv = (sy < -1.0f) || (sy > (float)HH) || (sx < -1.0f) || (sx > (float)WW);
        float r = 0.0f;
        if (!inv) {
            float y = fminf(fmaxf(sy, 0.0f), (float)(HH-1));
            float x = fminf(fmaxf(sx, 0.0f), (float)(WW-1));
            int y0 = (int)floorf(y), x0 = (int)floorf(x);
            int y1i = min(y0 + 1, HH-1), x1i = min(x0 + 1, WW-1);
            float ly = __fadd_rn(y, -(float)y0);
            float lx = __fadd_rn(x, -(float)x0);
            float hy = __fadd_rn(1.0f, -ly);
            float hx = __fadd_rn(1.0f, -lx);
            float v00 = fb[y0 *WW + x0 ];
            float v01 = fb[y0 *WW + x1i];
            float v10 = fb[y1i*WW + x0 ];
            float v11 = fb[y1i*WW + x1i];
            r = __fadd_rn(__fadd_rn(__fadd_rn(
                    __fmul_rn(__fmul_rn(hy,hx), v00),
                    __fmul_rn(__fmul_rn(hy,lx), v01)),
                    __fmul_rn(__fmul_rn(ly,hx), v10)),
                    __fmul_rn(__fmul_rn(ly,lx), v11));
        }
        g_roif[(size_t)j*FDIM + pt*CH + c] = r;   // pt-major: coalesced
    }
}

// ---------------- 8. permute w_fc1 rows (c*9+pt) -> (pt*256+c) ----------------
__global__ void k_permw(const float* __restrict__ wfc1) {
    int i = blockIdx.x * blockDim.x + threadIdx.x;
    if (i >= FDIM*HID) return;
    int rd = i / HID, n = i - rd*HID;
    int pt = rd / CH, c = rd - pt*CH;
    g_wp[i] = wfc1[(c*NA + pt)*HID + n];
}

// ---------------- 9. fc1 GEMM: (800x2304)@(2304x1024)+bias, ReLU ----------------
#define GBM 64
#define GBN 64
#define GBK 16
__global__ void __launch_bounds__(256) k_gemm1(const float* __restrict__ bias) {
    __shared__ float As[GBK][GBM + 4];   // padded (272B row stride: 16B-aligned, conflict-free)
    __shared__ float Bs[GBK][GBN];
    int bm = blockIdx.x * GBM, bn = blockIdx.y * GBN;
    int tid = threadIdx.x;
    int tx = tid & 15, ty = tid >> 4;
    int ar = tid >> 2, ak = (tid & 3) * 4;
    int br = tid >> 4, bc = (tid & 15) * 4;
    float acc[4][4];
    #pragma unroll
    for (int i = 0; i < 4; ++i)
        #pragma unroll
        for (int jj = 0; jj < 4; ++jj) acc[i][jj] = 0.0f;

    for (int k0 = 0; k0 < FDIM; k0 += GBK) {
        float4 av = make_float4(0.f, 0.f, 0.f, 0.f);
        int arow = bm + ar;
        if (arow < NDET)
            av = *(const float4*)(g_roif + (size_t)arow*FDIM + k0 + ak);
        As[ak+0][ar] = av.x; As[ak+1][ar] = av.y;
        As[ak+2][ar] = av.z; As[ak+3][ar] = av.w;
        *(float4*)&Bs[br][bc] = *(const float4*)(g_wp + (size_t)(k0+br)*HID + bn + bc);
        __syncthreads();
        #pragma unroll
        for (int kk = 0; kk < GBK; ++kk) {
            float a[4], bb[4];
            *(float4*)a  = *(const float4*)&As[kk][ty*4];
            *(float4*)bb = *(const float4*)&Bs[kk][tx*4];
            #pragma unroll
            for (int i = 0; i < 4; ++i)
                #pragma unroll
                for (int jj = 0; jj < 4; ++jj)
                    acc[i][jj] += a[i] * bb[jj];
        }
        __syncthreads();
    }
    #pragma unroll
    for (int i = 0; i < 4; ++i) {
        int row = bm + ty*4 + i;
        if (row >= NDET) continue;
        #pragma unroll
        for (int jj = 0; jj < 4; ++jj) {
            int col = bn + tx*4 + jj;
            float v = fmaxf(acc[i][jj] + bias[col], 0.0f);
            g_hdn[(size_t)row*HID + col] = v;
        }
    }
}

// ---------------- 10. stage2 heads: hdn @ w_cls (+b), hdn @ w_wh (+b) ----------------
__global__ void k_stage2(const float* __restrict__ wcls, const float* __restrict__ bcls,
                         const float* __restrict__ wwh,  const float* __restrict__ bwh,
                         float* __restrict__ out) {
    __shared__ float sh[HID];
    __shared__ float red[14][128];
    int j = blockIdx.x;
    int tid = threadIdx.x;   // 128
    for (int i = tid; i < HID; i += 128) sh[i] = g_hdn[(size_t)j*HID + i];
    __syncthreads();
    float acc[14];
    #pragma unroll
    for (int q = 0; q < 14; ++q) acc[q] = 0.0f;
    for (int i = tid; i < HID; i += 128) {
        float h = sh[i];
        #pragma unroll
        for (int q = 0; q < 10; ++q) acc[q]      += h * wcls[i*10 + q];
        #pragma unroll
        for (int q = 0; q < 4;  ++q) acc[10 + q] += h * wwh [i*4  + q];
    }
    #pragma unroll
    for (int q = 0; q < 14; ++q) red[q][tid] = acc[q];
    __syncthreads();
    if (tid < 14) {
        float s = 0.0f;
        #pragma unroll 8
        for (int t = 0; t < 128; ++t) s += red[tid][t];
        if (tid < 10) out[OFF_S2CLS + j*10 + tid]      = s + bcls[tid];
        else          out[OFF_S2WH  + j*4  + (tid-10)] = s + bwh[tid-10];
    }
}

// ---------------- launch ----------------
extern "C" void kernel_launch(void* const* d_in, const int* in_sizes, int n_in,
                              void* d_out, int out_size) {
    const float* feat  = (const float*)d_in[0];
    const float* hm    = (const float*)d_in[1];
    const float* wh    = (const float*)d_in[2];
    const float* offs  = (const float*)d_in[3];
    const float* wfc1  = (const float*)d_in[4];
    const float* bfc1  = (const float*)d_in[5];
    const float* wcls  = (const float*)d_in[6];
    const float* bcls  = (const float*)d_in[7];
    const float* wwh   = (const float*)d_in[8];
    const float* bwh   = (const float*)d_in[9];
    float* out = (float*)d_out;

    k_zero<<<(BS*NBINS + 255)/256, 256>>>();
    k_hist_copy<<<(HMTOT + 255)/256, 256>>>(hm, out);
    k_thresh<<<1, 32>>>();
    k_collect<<<(HMTOT + 255)/256, 256>>>(hm);
    k_select<<<BS, 256>>>();
    k_detect<<<(NDET + 255)/256, 256>>>(wh, offs, out);
    k_roi<<<NDET, CH>>>(feat);
    k_permw<<<(FDIM*HID + 255)/256, 256>>>(wfc1);
    dim3 g1((NDET + GBM - 1)/GBM, HID/GBN);
    k_gemm1<<<g1, 256>>>(bfc1);
    k_stage2<<<NDET, 128>>>(wcls, bcls, wwh, bwh, out);
}

// round 4
// speedup vs baseline: 1.6857x; 1.6857x over previous
#include <cuda_runtime.h>
#include <cuda_bf16.h>
#include <stdint.h>

#define BS 8
#define CH 256
#define HH 128
#define WW 128
#define HW (HH*WW)          /* 16384 */
#define NA 9
#define KTOP 100
#define NDET (BS*KTOP)      /* 800 */
#define FDIM (CH*NA)        /* 2304 */
#define KSPL (3*FDIM)       /* 6912 : [hi,hi,lo] x [hi,lo,hi] split */
#define MPAD 896            /* 7*128 */
#define HID 1024
#define NBINS 4096
#define CANDCAP 4096
#define BHW (NA*HW)         /* 147456 */
#define HMTOT (BS*BHW)      /* 1179648 */

// output offsets (floats)
#define OFF_HM    0
#define OFF_WH1   1179648
#define OFF_OFF1  1182848
#define OFF_CLS1  1184448
#define OFF_WH2   1185248
#define OFF_OFF2  1188448
#define OFF_S2CLS 1190048
#define OFF_S2WH  1198048
#define OFF_INDS  1201248
#define OFF_VAL   1202048

// ---------------- scratch ----------------
__device__ int                g_hist[BS*NBINS];
__device__ int                g_thresh[BS];
__device__ int                g_ccnt[BS];
__device__ unsigned long long g_cand[BS*CANDCAP];
__device__ float              g_tv[NDET];
__device__ int                g_ti[NDET];
__device__ float              g_boxes[NDET*4];
__device__ __align__(16) __nv_bfloat16 g_abf[MPAD*KSPL];   // A' [896][6912] (rows>=800 stay zero: .bss)
__device__ __align__(16) __nv_bfloat16 g_bbf[HID*KSPL];    // B' [1024][6912]
__device__ float              g_hdn[NDET*HID];

__device__ __forceinline__ uint32_t smem_u32(const void* p) {
    uint32_t a;
    asm("{ .reg .u64 t; cvta.to.shared.u64 t, %1; cvt.u32.u64 %0, t; }" : "=r"(a) : "l"(p));
    return a;
}
__device__ __forceinline__ void cp_async16(uint32_t d, const void* s) {
    unsigned long long g;
    asm("cvta.to.global.u64 %0, %1;" : "=l"(g) : "l"(s));
    asm volatile("cp.async.cg.shared.global [%0], [%1], 16;" :: "r"(d), "l"(g));
}
__device__ __forceinline__ void ldmatrix_x4(uint32_t* r, uint32_t addr) {
    asm volatile("ldmatrix.sync.aligned.m8n8.x4.shared.b16 {%0,%1,%2,%3}, [%4];"
        : "=r"(r[0]), "=r"(r[1]), "=r"(r[2]), "=r"(r[3]) : "r"(addr));
}
__device__ __forceinline__ void mma16816(float* d, const uint32_t* a, const uint32_t* b) {
    asm volatile("mma.sync.aligned.m16n8k16.row.col.f32.bf16.bf16.f32 "
        "{%0,%1,%2,%3}, {%4,%5,%6,%7}, {%8,%9}, {%0,%1,%2,%3};"
        : "+f"(d[0]), "+f"(d[1]), "+f"(d[2]), "+f"(d[3])
        : "r"(a[0]), "r"(a[1]), "r"(a[2]), "r"(a[3]), "r"(b[0]), "r"(b[1]));
}

// ---------------- 1. zero hist + counters ----------------
__global__ void k_zero() {
    int i = blockIdx.x * blockDim.x + threadIdx.x;
    if (i < BS*NBINS) g_hist[i] = 0;
    if (i < BS)       g_ccnt[i] = 0;
}

// ---------------- 2. copy hm to out + histogram ----------------
__global__ void k_hist_copy(const float* __restrict__ hm, float* __restrict__ out) {
    int i = blockIdx.x * blockDim.x + threadIdx.x;
    if (i >= HMTOT) return;
    float v = hm[i];
    out[OFF_HM + i] = v;
    int b = i / BHW;
    int bin = (int)(v * (float)NBINS);
    bin = bin < 0 ? 0 : (bin > NBINS-1 ? NBINS-1 : bin);
    atomicAdd(&g_hist[b*NBINS + bin], 1);
}

// ---------------- 3. threshold bin per batch ----------------
__global__ void k_thresh() {
    int b = threadIdx.x;
    if (b >= BS) return;
    int cum = 0, t = 0;
    for (int bin = NBINS-1; bin >= 0; --bin) {
        cum += g_hist[b*NBINS + bin];
        if (cum >= KTOP) { t = bin; break; }
    }
    g_thresh[b] = t;
}

// ---------------- 4. collect candidates ----------------
__global__ void k_collect(const float* __restrict__ hm) {
    int i = blockIdx.x * blockDim.x + threadIdx.x;
    if (i >= HMTOT) return;
    float v = hm[i];
    int b = i / BHW;
    int bin = (int)(v * (float)NBINS);
    bin = bin < 0 ? 0 : (bin > NBINS-1 ? NBINS-1 : bin);
    if (bin < g_thresh[b]) return;
    int il  = i - b*BHW;
    int a   = il / HW;
    int pix = il - a*HW;
    unsigned int iflat = (unsigned int)(pix * NA + a);
    unsigned int vb = __float_as_uint(v);
    unsigned long long key = ((unsigned long long)vb << 32) | (0xFFFFFFFFu - iflat);
    int pos = atomicAdd(&g_ccnt[b], 1);
    if (pos < CANDCAP) g_cand[b*CANDCAP + pos] = key;
}

// ---------------- 5. exact sorted top-100 per batch ----------------
__global__ void k_select() {
    __shared__ unsigned long long sk[CANDCAP];
    __shared__ unsigned long long wmax[8];
    __shared__ unsigned long long sbest;
    int b = blockIdx.x;
    int tid = threadIdx.x;
    int C = g_ccnt[b]; if (C > CANDCAP) C = CANDCAP;
    for (int i = tid; i < CANDCAP; i += 256)
        sk[i] = (i < C) ? g_cand[b*CANDCAP + i] : 0ULL;
    __syncthreads();
    int lane = tid & 31, wid = tid >> 5;
    for (int r = 0; r < KTOP; ++r) {
        unsigned long long best = 0ULL;
        for (int i = tid; i < C; i += 256) {
            unsigned long long k = sk[i];
            if (k > best) best = k;
        }
        #pragma unroll
        for (int o = 16; o > 0; o >>= 1) {
            unsigned long long other = __shfl_xor_sync(0xffffffffu, best, o);
            if (other > best) best = other;
        }
        if (lane == 0) wmax[wid] = best;
        __syncthreads();
        if (tid == 0) {
            unsigned long long m = wmax[0];
            #pragma unroll
            for (int w = 1; w < 8; ++w) if (wmax[w] > m) m = wmax[w];
            sbest = m;
        }
        __syncthreads();
        unsigned long long m = sbest;
        for (int i = tid; i < C; i += 256) {
            if (sk[i] == m) {
                sk[i] = 0ULL;
                g_tv[b*KTOP + r] = __uint_as_float((unsigned int)(m >> 32));
                g_ti[b*KTOP + r] = (int)(0xFFFFFFFFu - (unsigned int)(m & 0xFFFFFFFFu));
            }
        }
        __syncthreads();
    }
}

// ---------------- 6. detections ----------------
__global__ void k_detect(const float* __restrict__ wh, const float* __restrict__ offs,
                         float* __restrict__ out) {
    int j = blockIdx.x * blockDim.x + threadIdx.x;
    if (j >= NDET) return;
    int b = j / KTOP;
    float v   = g_tv[j];
    int iflat = g_ti[j];
    int cls1  = iflat % NA;
    int pos   = iflat / NA;
    int inds  = pos + b * HW;
    int a2 = inds % NA;
    int p2 = inds / NA;
    float w0 = wh[(a2*4+0)*HW + p2];
    float w1 = wh[(a2*4+1)*HW + p2];
    float w2 = wh[(a2*4+2)*HW + p2];
    float w3 = wh[(a2*4+3)*HW + p2];
    float o0 = offs[(a2*2+0)*HW + p2];
    float o1 = offs[(a2*2+1)*HW + p2];
    float xs = (float)(inds % WW) + o0;
    float ys = (float)(inds / WW) + o1;
    g_boxes[j*4+0] = xs + w0; g_boxes[j*4+1] = ys + w1;
    g_boxes[j*4+2] = xs + w2; g_boxes[j*4+3] = ys + w3;
    out[OFF_WH1 + j*4+0] = w0; out[OFF_WH1 + j*4+1] = w1;
    out[OFF_WH1 + j*4+2] = w2; out[OFF_WH1 + j*4+3] = w3;
    out[OFF_WH2 + j*4+0] = w0; out[OFF_WH2 + j*4+1] = w1;
    out[OFF_WH2 + j*4+2] = w2; out[OFF_WH2 + j*4+3] = w3;
    out[OFF_OFF1 + j*2+0] = o0; out[OFF_OFF1 + j*2+1] = o1;
    out[OFF_OFF2 + j*2+0] = o0; out[OFF_OFF2 + j*2+1] = o1;
    out[OFF_CLS1 + j] = (float)cls1;
    out[OFF_INDS + j] = (float)inds;
    out[OFF_VAL  + j] = v;
}

// ---------------- 7. ROI align 3x3 -> bf16 hi/lo split A' ----------------
__global__ void k_roi(const float* __restrict__ feat) {
    int j = blockIdx.x;
    int c = threadIdx.x;          // 256 channels
    int b = j / KTOP;
    float x1b = g_boxes[j*4+0], y1b = g_boxes[j*4+1];
    float x2b = g_boxes[j*4+2], y2b = g_boxes[j*4+3];
    float rw = fmaxf(x2b - x1b, 1.0f);
    float rh = fmaxf(y2b - y1b, 1.0f);
    float bw = rw / 3.0f;
    float bh = rh / 3.0f;
    const float* fb = feat + ((size_t)b*CH + c) * HW;
    #pragma unroll
    for (int pt = 0; pt < 9; ++pt) {
        int gy = pt / 3, gx = pt % 3;
        float sy = __fadd_rn(y1b, __fmul_rn((float)gy + 0.5f, bh));
        float sx = __fadd_rn(x1b, __fmul_rn((float)gx + 0.5f, bw));
        bool inv = (sy < -1.0f) || (sy > (float)HH) || (sx < -1.0f) || (sx > (float)WW);
        float r = 0.0f;
        if (!inv) {
            float y = fminf(fmaxf(sy, 0.0f), (float)(HH-1));
            float x = fminf(fmaxf(sx, 0.0f), (float)(WW-1));
            int y0 = (int)floorf(y), x0 = (int)floorf(x);
            int y1i = min(y0 + 1, HH-1), x1i = min(x0 + 1, WW-1);
            float ly = __fadd_rn(y, -(float)y0);
            float lx = __fadd_rn(x, -(float)x0);
            float hy = __fadd_rn(1.0f, -ly);
            float hx = __fadd_rn(1.0f, -lx);
            float v00 = fb[y0 *WW + x0 ];
            float v01 = fb[y0 *WW + x1i];
            float v10 = fb[y1i*WW + x0 ];
            float v11 = fb[y1i*WW + x1i];
            r = __fadd_rn(__fadd_rn(__fadd_rn(
                    __fmul_rn(__fmul_rn(hy,hx), v00),
                    __fmul_rn(__fmul_rn(hy,lx), v01)),
                    __fmul_rn(__fmul_rn(ly,hx), v10)),
                    __fmul_rn(__fmul_rn(ly,lx), v11));
        }
        __nv_bfloat16 hi = __float2bfloat16(r);
        __nv_bfloat16 lo = __float2bfloat16(__fadd_rn(r, -__bfloat162float(hi)));
        size_t base = (size_t)j*KSPL + 3*(pt*CH + c);
        g_abf[base+0] = hi;
        g_abf[base+1] = hi;
        g_abf[base+2] = lo;
    }
}

// ---------------- 8. B' prep: permute + transpose + bf16 split ----------------
__global__ void k_prepB(const float* __restrict__ wfc1) {
    __shared__ float s[32][33];
    int t0 = blockIdx.x * 32, n0 = blockIdx.y * 32;
    int tid = threadIdx.x;
    int sub = tid >> 5, nn = tid & 31;
    #pragma unroll
    for (int q = 0; q < 4; ++q) {
        int tl = sub + q*8;
        int t = t0 + tl;
        int pt = t >> 8, c = t & 255;
        s[tl][nn] = wfc1[(size_t)(c*NA + pt)*HID + n0 + nn];
    }
    __syncthreads();
    #pragma unroll
    for (int q = 0; q < 4; ++q) {
        int nl = sub + q*8;
        int tl = nn;
        float v = s[tl][nl];
        __nv_bfloat16 hi = __float2bfloat16(v);
        __nv_bfloat16 lo = __float2bfloat16(v - __bfloat162float(hi));
        size_t base = (size_t)(n0 + nl)*KSPL + 3*(t0 + tl);
        g_bbf[base+0] = hi;
        g_bbf[base+1] = lo;
        g_bbf[base+2] = hi;
    }
}

// ---------------- 9. fc1 GEMM: mma.sync bf16, 128x64 CTA tile ----------------
#define BM 128
#define BN 64
#define STAGE_BYTES 24576     /* A 16KB + B 8KB */
#define KT_TOTAL (KSPL/64)    /* 108 */
__global__ void __launch_bounds__(256) k_gemm_mma(const float* __restrict__ bias) {
    __shared__ __align__(1024) char smem[2*STAGE_BYTES];
    int tid = threadIdx.x, lane = tid & 31, w = tid >> 5;
    int bm = blockIdx.x * BM, bn = blockIdx.y * BN;
    int wm = w >> 1, wn = w & 1;

    const char* aG = (const char*)g_abf + (size_t)bm * (KSPL*2);
    const char* bG = (const char*)g_bbf + (size_t)bn * (KSPL*2);

    float acc[2][4][4];
    #pragma unroll
    for (int mi = 0; mi < 2; ++mi)
        #pragma unroll
        for (int ni = 0; ni < 4; ++ni)
            #pragma unroll
            for (int e = 0; e < 4; ++e) acc[mi][ni][e] = 0.0f;

    // precompute per-thread copy coords
    // A: 1024 chunks/stage, 4 per thread; B: 512 chunks, 2 per thread
    #define ISSUE_STAGE(kt, st) do {                                           \
        char* As_ = smem + (st)*STAGE_BYTES;                                   \
        char* Bs_ = As_ + 16384;                                               \
        _Pragma("unroll")                                                      \
        for (int q = 0; q < 4; ++q) {                                          \
            int id = tid + q*256;                                              \
            int r = id >> 3, c = id & 7;                                       \
            uint32_t d = smem_u32(As_ + r*128 + ((c ^ (r & 7)) * 16));         \
            cp_async16(d, aG + (size_t)r*(KSPL*2) + (kt)*128 + c*16);          \
        }                                                                      \
        _Pragma("unroll")                                                      \
        for (int q = 0; q < 2; ++q) {                                          \
            int id = tid + q*256;                                              \
            int r = id >> 3, c = id & 7;                                       \
            uint32_t d = smem_u32(Bs_ + r*128 + ((c ^ (r & 7)) * 16));         \
            cp_async16(d, bG + (size_t)r*(KSPL*2) + (kt)*128 + c*16);          \
        }                                                                      \
        asm volatile("cp.async.commit_group;" ::: "memory");                   \
    } while (0)

    ISSUE_STAGE(0, 0);

    for (int kt = 0; kt < KT_TOTAL; ++kt) {
        int st = kt & 1;
        if (kt + 1 < KT_TOTAL) {
            ISSUE_STAGE(kt + 1, st ^ 1);
            asm volatile("cp.async.wait_group 1;" ::: "memory");
        } else {
            asm volatile("cp.async.wait_group 0;" ::: "memory");
        }
        __syncthreads();

        char* As = smem + st*STAGE_BYTES;
        char* Bs = As + 16384;
        #pragma unroll
        for (int kk = 0; kk < 4; ++kk) {
            uint32_t a[2][4];
            #pragma unroll
            for (int mi = 0; mi < 2; ++mi) {
                int r = wm*32 + mi*16 + (lane & 15);
                int c = kk*2 + (lane >> 4);
                ldmatrix_x4(a[mi], smem_u32(As + r*128 + ((c ^ (r & 7)) * 16)));
            }
            uint32_t b[2][4];
            #pragma unroll
            for (int nj = 0; nj < 2; ++nj) {
                int grp = lane >> 3;
                int r = wn*32 + nj*16 + (grp >> 1)*8 + (lane & 7);
                int c = kk*2 + (grp & 1);
                ldmatrix_x4(b[nj], smem_u32(Bs + r*128 + ((c ^ (r & 7)) * 16)));
            }
            #pragma unroll
            for (int mi = 0; mi < 2; ++mi)
                #pragma unroll
                for (int ni = 0; ni < 4; ++ni)
                    mma16816(acc[mi][ni], a[mi], &b[ni >> 1][(ni & 1) * 2]);
        }
        __syncthreads();
    }

    // epilogue: bias + relu -> g_hdn (rows < NDET only)
    int row0 = bm + wm*32;
    int col0 = bn + wn*32;
    #pragma unroll
    for (int mi = 0; mi < 2; ++mi) {
        #pragma unroll
        for (int ni = 0; ni < 4; ++ni) {
            int ccol = col0 + ni*8 + (lane & 3)*2;
            float b0 = bias[ccol], b1 = bias[ccol+1];
            int r = row0 + mi*16 + (lane >> 2);
            if (r < NDET) {
                float2 v;
                v.x = fmaxf(acc[mi][ni][0] + b0, 0.0f);
                v.y = fmaxf(acc[mi][ni][1] + b1, 0.0f);
                *(float2*)&g_hdn[(size_t)r*HID + ccol] = v;
            }
            if (r + 8 < NDET) {
                float2 v;
                v.x = fmaxf(acc[mi][ni][2] + b0, 0.0f);
                v.y = fmaxf(acc[mi][ni][3] + b1, 0.0f);
                *(float2*)&g_hdn[(size_t)(r+8)*HID + ccol] = v;
            }
        }
    }
}

// ---------------- 10. stage2 heads ----------------
__global__ void k_stage2(const float* __restrict__ wcls, const float* __restrict__ bcls,
                         const float* __restrict__ wwh,  const float* __restrict__ bwh,
                         float* __restrict__ out) {
    __shared__ float sh[HID];
    __shared__ float red[14][128];
    int j = blockIdx.x;
    int tid = threadIdx.x;   // 128
    for (int i = tid; i < HID; i += 128) sh[i] = g_hdn[(size_t)j*HID + i];
    __syncthreads();
    float acc[14];
    #pragma unroll
    for (int q = 0; q < 14; ++q) acc[q] = 0.0f;
    for (int i = tid; i < HID; i += 128) {
        float h = sh[i];
        #pragma unroll
        for (int q = 0; q < 10; ++q) acc[q]      += h * wcls[i*10 + q];
        #pragma unroll
        for (int q = 0; q < 4;  ++q) acc[10 + q] += h * wwh [i*4  + q];
    }
    #pragma unroll
    for (int q = 0; q < 14; ++q) red[q][tid] = acc[q];
    __syncthreads();
    if (tid < 14) {
        float s = 0.0f;
        #pragma unroll 8
        for (int t = 0; t < 128; ++t) s += red[tid][t];
        if (tid < 10) out[OFF_S2CLS + j*10 + tid]      = s + bcls[tid];
        else          out[OFF_S2WH  + j*4  + (tid-10)] = s + bwh[tid-10];
    }
}

// ---------------- launch ----------------
extern "C" void kernel_launch(void* const* d_in, const int* in_sizes, int n_in,
                              void* d_out, int out_size) {
    const float* feat  = (const float*)d_in[0];
    const float* hm    = (const float*)d_in[1];
    const float* wh    = (const float*)d_in[2];
    const float* offs  = (const float*)d_in[3];
    const float* wfc1  = (const float*)d_in[4];
    const float* bfc1  = (const float*)d_in[5];
    const float* wcls  = (const float*)d_in[6];
    const float* bcls  = (const float*)d_in[7];
    const float* wwh   = (const float*)d_in[8];
    const float* bwh   = (const float*)d_in[9];
    float* out = (float*)d_out;

    k_zero<<<(BS*NBINS + 255)/256, 256>>>();
    k_prepB<<<dim3(FDIM/32, HID/32), 256>>>(wfc1);
    k_hist_copy<<<(HMTOT + 255)/256, 256>>>(hm, out);
    k_thresh<<<1, 32>>>();
    k_collect<<<(HMTOT + 255)/256, 256>>>(hm);
    k_select<<<BS, 256>>>();
    k_detect<<<(NDET + 255)/256, 256>>>(wh, offs, out);
    k_roi<<<NDET, CH>>>(feat);
    k_gemm_mma<<<dim3(MPAD/BM, HID/BN), 256>>>(bfc1);
    k_stage2<<<NDET, 128>>>(wcls, bcls, wwh, bwh, out);
}